// round 13
// baseline (speedup 1.0000x reference)
#include <cuda_runtime.h>

// PositionalEncoding: out[b,s,d] = x[b,s,d] + pe[s,d]
//   pe[s, 2i]   = sin(s / 10000^(2i/D))
//   pe[s, 2i+1] = cos(s / 10000^(2i/D))
// B=4, S=4096, D=2048, fp32.
//
// HBM-bound: 268 MB traffic. pe is recomputed in-register (free, hidden under
// memory latency) and reused across the 4 batches by each thread.

#define B_ 4
#define S_ 4096
#define D_ 2048

// One thread per float4 of the [S, D] plane: handles d = 4q .. 4q+3,
// i.e. sin/cos pairs i0 = 2q and i1 = 2q+1, for all 4 batches.
__global__ __launch_bounds__(256) void pe_add_kernel(
    const float4* __restrict__ x, float4* __restrict__ out)
{
    const int idx = blockIdx.x * blockDim.x + threadIdx.x; // 0 .. S*D/4 - 1
    const int stride4 = S_ * (D_ / 4);                     // float4s per batch

    const int s = idx >> 9;        // D/4 = 512
    const int q = idx & 511;

    // Issue all 4 batch loads up front (MLP=4) so the transcendental chain
    // below overlaps DRAM latency.
    float4 v0 = x[idx];
    float4 v1 = x[idx + 1 * stride4];
    float4 v2 = x[idx + 2 * stride4];
    float4 v3 = x[idx + 3 * stride4];

    // angle_i = s * 10000^(-2i/D) = s * exp2( -log2(10000)/1024 * i )
    const float K = -0.0129762813f;  // -log2(10000) / 1024
    const float fi0 = (float)(2 * q);
    const float fs  = (float)s;
    const float a0 = fs * exp2f(K * fi0);
    const float a1 = fs * exp2f(K * (fi0 + 1.0f));

    float s0, c0, s1, c1;
    sincosf(a0, &s0, &c0);   // fast path: |a| <= 4095 << Payne-Hanek threshold
    sincosf(a1, &s1, &c1);

    v0.x += s0; v0.y += c0; v0.z += s1; v0.w += c1;
    v1.x += s0; v1.y += c0; v1.z += s1; v1.w += c1;
    v2.x += s0; v2.y += c0; v2.z += s1; v2.w += c1;
    v3.x += s0; v3.y += c0; v3.z += s1; v3.w += c1;

    out[idx]               = v0;
    out[idx + 1 * stride4] = v1;
    out[idx + 2 * stride4] = v2;
    out[idx + 3 * stride4] = v3;
}

extern "C" void kernel_launch(void* const* d_in, const int* in_sizes, int n_in,
                              void* d_out, int out_size)
{
    const float4* x   = (const float4*)d_in[0];
    float4*       out = (float4*)d_out;

    const int n4 = S_ * D_ / 4;          // 2,097,152 threads
    const int threads = 256;
    const int blocks = n4 / threads;     // 8192 blocks

    pe_add_kernel<<<blocks, threads>>>(x, out);
}